// round 15
// baseline (speedup 1.0000x reference)
#include <cuda_runtime.h>
#include <math.h>

#define Bb 2
#define Ls 2048
#define Hh 16
#define Ee 64
#define BQ 128
#define BK 64
#define NEL ((size_t)Bb * Ls * Hh * Ee)
#define SCALE_LOG2E (0.125f * 1.4426950408889634f)
#define PW 72                 // 16-bit smem tile pitch (144B rows: conflict-free ldmatrix)

typedef unsigned int  u32;
typedef unsigned short u16;

// fp16 hi/lo planes, precomputed once per launch
__device__ u16 gQh[NEL], gQl[NEL], gKh[NEL], gKl[NEL], gVh[NEL], gVl[NEL];

__device__ __forceinline__ u32 sm32(const void* p) {
    return (u32)__cvta_generic_to_shared(p);
}
__device__ __forceinline__ void ldsm4(u32& r0, u32& r1, u32& r2, u32& r3, u32 a) {
    asm volatile("ldmatrix.sync.aligned.m8n8.x4.shared.b16 {%0,%1,%2,%3},[%4];"
                 : "=r"(r0), "=r"(r1), "=r"(r2), "=r"(r3) : "r"(a));
}
__device__ __forceinline__ void ldsm4t(u32& r0, u32& r1, u32& r2, u32& r3, u32 a) {
    asm volatile("ldmatrix.sync.aligned.m8n8.x4.trans.shared.b16 {%0,%1,%2,%3},[%4];"
                 : "=r"(r0), "=r"(r1), "=r"(r2), "=r"(r3) : "r"(a));
}
__device__ __forceinline__ void mma16816(float* d, const u32* a, u32 b0, u32 b1) {
    asm volatile("mma.sync.aligned.m16n8k16.row.col.f32.f16.f16.f32 "
                 "{%0,%1,%2,%3},{%4,%5,%6,%7},{%8,%9},{%0,%1,%2,%3};"
                 : "+f"(d[0]), "+f"(d[1]), "+f"(d[2]), "+f"(d[3])
                 : "r"(a[0]), "r"(a[1]), "r"(a[2]), "r"(a[3]), "r"(b0), "r"(b1));
}
__device__ __forceinline__ float half_rt(float x) {
    float y;
    asm("{\n\t.reg .b16 h;\n\tcvt.rn.f16.f32 h, %1;\n\tcvt.f32.f16 %0, h;\n\t}"
        : "=f"(y) : "f"(x));
    return y;
}
// pack two floats as fp16x2: first arg -> low half
__device__ __forceinline__ u32 f16x2(float lo, float hi) {
    u32 r;
    asm("cvt.rn.f16x2.f32 %0, %1, %2;" : "=r"(r) : "f"(hi), "f"(lo));
    return r;
}
__device__ __forceinline__ float ex2(float x) {
    float y;
    asm("ex2.approx.f32 %0, %1;" : "=f"(y) : "f"(x));
    return y;
}
#define CPA(dst, src) \
    asm volatile("cp.async.cg.shared.global [%0], [%1], 16;" :: "r"(dst), "l"(src))

// ---------------- prep: fp32 -> fp16 hi/lo planes (Q pre-scaled) ----------------
__global__ __launch_bounds__(256)
void prep(const float* __restrict__ Q, const float* __restrict__ K,
          const float* __restrict__ V)
{
    size_t i = ((size_t)blockIdx.x * 256 + threadIdx.x) * 4;
    float4 q = *(const float4*)(Q + i);
    float4 k = *(const float4*)(K + i);
    float4 v = *(const float4*)(V + i);
    float qs[4], ks[4], vs[4];
    qs[0] = q.x * SCALE_LOG2E; qs[1] = q.y * SCALE_LOG2E;
    qs[2] = q.z * SCALE_LOG2E; qs[3] = q.w * SCALE_LOG2E;
    ks[0] = k.x; ks[1] = k.y; ks[2] = k.z; ks[3] = k.w;
    vs[0] = v.x; vs[1] = v.y; vs[2] = v.z; vs[3] = v.w;
    float qh[4], ql[4], kh[4], kl[4], vh[4], vl[4];
    #pragma unroll
    for (int j = 0; j < 4; j++) {
        qh[j] = half_rt(qs[j]); ql[j] = qs[j] - qh[j];
        kh[j] = half_rt(ks[j]); kl[j] = ks[j] - kh[j];
        vh[j] = half_rt(vs[j]); vl[j] = vs[j] - vh[j];
    }
    uint2 t;
    t.x = f16x2(qh[0], qh[1]); t.y = f16x2(qh[2], qh[3]); *(uint2*)&gQh[i] = t;
    t.x = f16x2(ql[0], ql[1]); t.y = f16x2(ql[2], ql[3]); *(uint2*)&gQl[i] = t;
    t.x = f16x2(kh[0], kh[1]); t.y = f16x2(kh[2], kh[3]); *(uint2*)&gKh[i] = t;
    t.x = f16x2(kl[0], kl[1]); t.y = f16x2(kl[2], kl[3]); *(uint2*)&gKl[i] = t;
    t.x = f16x2(vh[0], vh[1]); t.y = f16x2(vh[2], vh[3]); *(uint2*)&gVh[i] = t;
    t.x = f16x2(vl[0], vl[1]); t.y = f16x2(vl[2], vl[3]); *(uint2*)&gVl[i] = t;
}

// Q/K/V: [B, L, H, E] -> ((b*L + l)*H + h)*E + e   (row stride H*E = 1024)
// A:     [B, H, L, S];  O: [B, L, H, E]

__global__ __launch_bounds__(256, 2)
void attn(float* __restrict__ O, float* __restrict__ A)
{
    extern __shared__ char smraw[];
    u16* Qh = (u16*)smraw;             // [128][PW]
    u16* Ql = Qh + 128 * PW;
    u16* Kh = Ql + 128 * PW;           // [64][PW]  rows = n, cols = e
    u16* Kl = Kh + 64 * PW;
    u16* Vh = Kl + 64 * PW;            // [64][PW]  rows = s, cols = e (trans-loaded)
    u16* Vl = Vh + 64 * PW;
    u16* Ph = Vl + 64 * PW;            // [128][PW] rows = m, cols = s
    float* Zs = (float*)(Ph + 128 * PW);   // [128]

    const int mt  = (Ls / BQ - 1) - blockIdx.x;    // heavy tiles launch first
    const int h   = blockIdx.y, b = blockIdx.z;
    const int tid = threadIdx.x;
    const int l   = tid & 31, wid = tid >> 5;
    const int wm  = wid >> 1, wn = wid & 1;        // 4 x 2 warp grid, 32x32 tiles
    const int m0  = mt * BQ;
    const int bh  = b * Hh + h;

    const size_t qoff = (((size_t)b * Ls + m0) * Hh + h) * Ee;
    const size_t koff = ((size_t)b * Ls * Hh + h) * Ee;
    float* Ab = A + ((size_t)bh * Ls + m0) * (size_t)Ls;

    // ---- async-copy Q tile (2 planes x 128 rows x 128B) ----
    {
        #pragma unroll
        for (int p = 0; p < 8; p++) {
            int cc  = tid + (p & 3) * 256;          // 0..1023
            int row = cc >> 3, seg = cc & 7;
            const u16* src = (p < 4 ? gQh : gQl) + qoff + (size_t)row * 1024 + seg * 8;
            u16* dst = (p < 4 ? Qh : Ql) + row * PW + seg * 8;
            CPA(sm32(dst), src);
        }
    }
    if (tid < 128) Zs[tid] = 0.f;

    // ---- zero-fill fully masked A columns [m0+BQ, Ls) ----
    if (m0 + BQ < Ls) {
        int c0  = m0 + BQ;
        int w4  = (Ls - c0) >> 2;
        int tot = BQ * w4;
        for (int idx = tid; idx < tot; idx += 256) {
            int r  = idx / w4;
            int c4 = idx - r * w4;
            *(float4*)(Ab + (size_t)r * Ls + c0 + c4 * 4) = make_float4(0.f, 0.f, 0.f, 0.f);
        }
    }

    float zp[4];
    zp[0] = zp[1] = zp[2] = zp[3] = 0.f;
    float oacc[2][4][4];
    #pragma unroll
    for (int i = 0; i < 2; i++)
        #pragma unroll
        for (int j = 0; j < 4; j++)
            #pragma unroll
            for (int k = 0; k < 4; k++) oacc[i][j][k] = 0.f;

    const u32 uQh = sm32(Qh), uQl = sm32(Ql);
    const u32 uKh = sm32(Kh), uKl = sm32(Kl);
    const u32 uVh = sm32(Vh), uVl = sm32(Vl);
    const u32 uPh = sm32(Ph);
    // ldmatrix offsets (bytes)
    const u32 aOff = ((32 * wm + (l & 15)) * PW + 8 * (l >> 4)) * 2;
    const u32 bOff = ((32 * wn + 8 * ((l >> 3) & 1) + (l & 7)) * PW + 8 * (l >> 4)) * 2;
    const u32 vOff = (((l & 7) + 8 * (l >> 4)) * PW + 32 * wn + 8 * ((l >> 3) & 1)) * 2;

    const int ntiles = 2 * mt + 2;
    for (int nt = 0; nt < ntiles; nt++) {
        __syncthreads();     // previous iteration's smem consumers done
        // ---- async-copy K,V tiles (4 planes x 64 rows x 128B) ----
        #pragma unroll
        for (int p = 0; p < 8; p++) {
            int cc  = tid + (p & 1) * 256;          // 0..511
            int row = cc >> 3, seg = cc & 7;
            const u16* srcb = (p < 2 ? gKh : p < 4 ? gKl : p < 6 ? gVh : gVl);
            u16* dstb       = (p < 2 ? Kh  : p < 4 ? Kl  : p < 6 ? Vh  : Vl);
            const u16* src = srcb + koff + (size_t)(nt * BK + row) * 1024 + seg * 8;
            CPA(sm32(dstb + row * PW + seg * 8), src);
        }
        asm volatile("cp.async.commit_group;");
        asm volatile("cp.async.wait_group 0;");
        __syncthreads();

        // ---- S = Q K^T via fp16x3 mma (32x32 warp tile) ----
        float sacc[2][4][4];
        #pragma unroll
        for (int i = 0; i < 2; i++)
            #pragma unroll
            for (int j = 0; j < 4; j++)
                #pragma unroll
                for (int k = 0; k < 4; k++) sacc[i][j][k] = 0.f;

        #pragma unroll
        for (int ks = 0; ks < 4; ks++) {
            u32 ah[2][4], al[2][4], bhr[8], blr[8];
            ldsm4(ah[0][0], ah[0][1], ah[0][2], ah[0][3], uQh + aOff + ks * 32);
            ldsm4(ah[1][0], ah[1][1], ah[1][2], ah[1][3], uQh + aOff + 16 * PW * 2 + ks * 32);
            ldsm4(al[0][0], al[0][1], al[0][2], al[0][3], uQl + aOff + ks * 32);
            ldsm4(al[1][0], al[1][1], al[1][2], al[1][3], uQl + aOff + 16 * PW * 2 + ks * 32);
            ldsm4(bhr[0], bhr[1], bhr[2], bhr[3], uKh + bOff + ks * 32);
            ldsm4(bhr[4], bhr[5], bhr[6], bhr[7], uKh + bOff + 16 * PW * 2 + ks * 32);
            ldsm4(blr[0], blr[1], blr[2], blr[3], uKl + bOff + ks * 32);
            ldsm4(blr[4], blr[5], blr[6], blr[7], uKl + bOff + 16 * PW * 2 + ks * 32);
            #pragma unroll
            for (int am = 0; am < 2; am++)
                #pragma unroll
                for (int an = 0; an < 4; an++) {
                    int g = (an >> 1) * 4 + (an & 1);
                    mma16816(sacc[am][an], ah[am], bhr[g], bhr[g + 2]);   // hi*hi
                    mma16816(sacc[am][an], ah[am], blr[g], blr[g + 2]);   // hi*lo
                    mma16816(sacc[am][an], al[am], bhr[g], bhr[g + 2]);   // lo*hi
                }
        }

        // ---- exp2, causal mask, Z partials, A write, P (fp16) -> smem ----
        const int n0 = nt * BK;
        const bool diag = (nt >= 2 * mt);
        #pragma unroll
        for (int am = 0; am < 2; am++) {
            #pragma unroll
            for (int an = 0; an < 4; an++) {
                float* d = sacc[am][an];
                int rl0 = 32 * wm + 16 * am + (l >> 2);
                int c   = 32 * wn + 8 * an + 2 * (l & 3);
                int gr0 = m0 + rl0, gc = n0 + c;
                float p0 = ex2(d[0]), p1 = ex2(d[1]);
                float p2 = ex2(d[2]), p3 = ex2(d[3]);
                if (diag) {
                    if (gc     > gr0)     p0 = 0.f;
                    if (gc + 1 > gr0)     p1 = 0.f;
                    if (gc     > gr0 + 8) p2 = 0.f;
                    if (gc + 1 > gr0 + 8) p3 = 0.f;
                }
                zp[2 * am]     += p0 + p1;
                zp[2 * am + 1] += p2 + p3;
                *(float2*)(Ab + (size_t)rl0 * Ls + gc)       = make_float2(p0, p1);
                *(float2*)(Ab + (size_t)(rl0 + 8) * Ls + gc) = make_float2(p2, p3);
                *(u32*)&Ph[rl0 * PW + c]       = f16x2(p0, p1);
                *(u32*)&Ph[(rl0 + 8) * PW + c] = f16x2(p2, p3);
            }
        }
        __syncthreads();

        // ---- O += P V via fp16 2-term mma (P * (V_hi + V_lo)) ----
        #pragma unroll
        for (int ks = 0; ks < 4; ks++) {
            u32 ah[2][4], bhr[8], blr[8];
            ldsm4(ah[0][0], ah[0][1], ah[0][2], ah[0][3], uPh + aOff + ks * 32);
            ldsm4(ah[1][0], ah[1][1], ah[1][2], ah[1][3], uPh + aOff + 16 * PW * 2 + ks * 32);
            ldsm4t(bhr[0], bhr[1], bhr[2], bhr[3], uVh + vOff + ks * 16 * PW * 2);
            ldsm4t(bhr[4], bhr[5], bhr[6], bhr[7], uVh + vOff + ks * 16 * PW * 2 + 32);
            ldsm4t(blr[0], blr[1], blr[2], blr[3], uVl + vOff + ks * 16 * PW * 2);
            ldsm4t(blr[4], blr[5], blr[6], blr[7], uVl + vOff + ks * 16 * PW * 2 + 32);
            #pragma unroll
            for (int am = 0; am < 2; am++)
                #pragma unroll
                for (int an = 0; an < 4; an++) {
                    int g = (an >> 1) * 4 + (an & 1);
                    mma16816(oacc[am][an], ah[am], bhr[g], bhr[g + 2]);
                    mma16816(oacc[am][an], ah[am], blr[g], blr[g + 2]);
                }
        }
    }

    // ---- Z reduction: quad shfl + smem atomics ----
    #pragma unroll
    for (int i = 0; i < 4; i++) {
        float z = zp[i];
        z += __shfl_xor_sync(0xffffffffu, z, 1);
        z += __shfl_xor_sync(0xffffffffu, z, 2);
        if ((l & 3) == 0) {
            int rl = 32 * wm + 16 * (i >> 1) + (l >> 2) + 8 * (i & 1);
            atomicAdd(&Zs[rl], z);
        }
    }
    __syncthreads();
    if (tid < 128) Zs[tid] = 1.0f / Zs[tid];
    __syncthreads();

    // ---- O epilogue (scaled by 1/Z) ----
    const int bO = (int)blockIdx.z, hO = (int)blockIdx.y;
    #pragma unroll
    for (int am = 0; am < 2; am++) {
        int rl0 = 32 * wm + 16 * am + (l >> 2);
        float zi0 = Zs[rl0], zi1 = Zs[rl0 + 8];
        int gr0 = m0 + rl0;
        #pragma unroll
        for (int an = 0; an < 4; an++) {
            float* d = oacc[am][an];
            int e = 32 * wn + 8 * an + 2 * (l & 3);
            *(float2*)(O + (((size_t)bO * Ls + gr0) * Hh + hO) * Ee + e) =
                make_float2(d[0] * zi0, d[1] * zi0);
            *(float2*)(O + (((size_t)bO * Ls + gr0 + 8) * Hh + hO) * Ee + e) =
                make_float2(d[2] * zi1, d[3] * zi1);
        }
    }

    // ---- fused A normalization (this block's rows, lower-triangular span) ----
    {
        int w4 = (mt + 1) * 32;   // float4s per row
        for (int r = wid; r < 128; r += 8) {
            float zi = Zs[r];
            float4* row = (float4*)(Ab + (size_t)r * Ls);
            for (int c4 = l; c4 < w4; c4 += 32) {
                float4 v = row[c4];
                v.x *= zi; v.y *= zi; v.z *= zi; v.w *= zi;
                row[c4] = v;
            }
        }
    }
}

extern "C" void kernel_launch(void* const* d_in, const int* in_sizes, int n_in,
                              void* d_out, int out_size) {
    const float* Q = (const float*)d_in[0];
    const float* K = (const float*)d_in[1];
    const float* V = (const float*)d_in[2];
    float* O = (float*)d_out;
    float* A = (float*)d_out + (size_t)Bb * Ls * Hh * Ee;   // tuple order: (V, A)

    prep<<<(int)(NEL / 4 / 256), 256>>>(Q, K, V);

    int smem = (3 * 128 + 4 * 64) * PW * 2 + 128 * 4;   // tiles + Zs = ~92.7 KB
    cudaFuncSetAttribute(attn, cudaFuncAttributeMaxDynamicSharedMemorySize, smem);
    dim3 grid(Ls / BQ, Hh, Bb);   // 16 x 16 x 2 = 512 blocks, heavy-first
    attn<<<grid, 256, smem>>>(O, A);
}

// round 17
// speedup vs baseline: 1.1594x; 1.1594x over previous
#include <cuda_runtime.h>
#include <math.h>

#define Bb 2
#define Ls 2048
#define Hh 16
#define Ee 64
#define BQ 64
#define BK 64
#define NEL ((size_t)Bb * Ls * Hh * Ee)
#define SCALE_LOG2E (0.125f * 1.4426950408889634f)
#define PW 72                 // 16-bit smem tile pitch (144B rows: conflict-free ldmatrix)
#define PLANE (64 * PW)       // u16 elements per tile plane

typedef unsigned int  u32;
typedef unsigned short u16;

// fp16 hi/lo planes, precomputed once per launch
__device__ u16 gQh[NEL], gQl[NEL], gKh[NEL], gKl[NEL], gVh[NEL], gVl[NEL];

__device__ __forceinline__ u32 sm32(const void* p) {
    return (u32)__cvta_generic_to_shared(p);
}
__device__ __forceinline__ void ldsm4(u32& r0, u32& r1, u32& r2, u32& r3, u32 a) {
    asm volatile("ldmatrix.sync.aligned.m8n8.x4.shared.b16 {%0,%1,%2,%3},[%4];"
                 : "=r"(r0), "=r"(r1), "=r"(r2), "=r"(r3) : "r"(a));
}
__device__ __forceinline__ void ldsm4t(u32& r0, u32& r1, u32& r2, u32& r3, u32 a) {
    asm volatile("ldmatrix.sync.aligned.m8n8.x4.trans.shared.b16 {%0,%1,%2,%3},[%4];"
                 : "=r"(r0), "=r"(r1), "=r"(r2), "=r"(r3) : "r"(a));
}
__device__ __forceinline__ void mma16816(float* d, const u32* a, u32 b0, u32 b1) {
    asm volatile("mma.sync.aligned.m16n8k16.row.col.f32.f16.f16.f32 "
                 "{%0,%1,%2,%3},{%4,%5,%6,%7},{%8,%9},{%0,%1,%2,%3};"
                 : "+f"(d[0]), "+f"(d[1]), "+f"(d[2]), "+f"(d[3])
                 : "r"(a[0]), "r"(a[1]), "r"(a[2]), "r"(a[3]), "r"(b0), "r"(b1));
}
__device__ __forceinline__ float half_rt(float x) {
    float y;
    asm("{\n\t.reg .b16 h;\n\tcvt.rn.f16.f32 h, %1;\n\tcvt.f32.f16 %0, h;\n\t}"
        : "=f"(y) : "f"(x));
    return y;
}
// pack two floats as fp16x2: first arg -> low half
__device__ __forceinline__ u32 f16x2(float lo, float hi) {
    u32 r;
    asm("cvt.rn.f16x2.f32 %0, %1, %2;" : "=r"(r) : "f"(hi), "f"(lo));
    return r;
}
__device__ __forceinline__ float ex2(float x) {
    float y;
    asm("ex2.approx.f32 %0, %1;" : "=f"(y) : "f"(x));
    return y;
}
#define CPA(dst, src) \
    asm volatile("cp.async.cg.shared.global [%0], [%1], 16;" :: "r"(dst), "l"(src))

// ---------------- prep: fp32 -> fp16 hi/lo planes (Q pre-scaled) ----------------
__global__ __launch_bounds__(256)
void prep(const float* __restrict__ Q, const float* __restrict__ K,
          const float* __restrict__ V)
{
    size_t i = ((size_t)blockIdx.x * 256 + threadIdx.x) * 4;
    float4 q = *(const float4*)(Q + i);
    float4 k = *(const float4*)(K + i);
    float4 v = *(const float4*)(V + i);
    float qs[4], ks[4], vs[4];
    qs[0] = q.x * SCALE_LOG2E; qs[1] = q.y * SCALE_LOG2E;
    qs[2] = q.z * SCALE_LOG2E; qs[3] = q.w * SCALE_LOG2E;
    ks[0] = k.x; ks[1] = k.y; ks[2] = k.z; ks[3] = k.w;
    vs[0] = v.x; vs[1] = v.y; vs[2] = v.z; vs[3] = v.w;
    float qh[4], ql[4], kh[4], kl[4], vh[4], vl[4];
    #pragma unroll
    for (int j = 0; j < 4; j++) {
        qh[j] = half_rt(qs[j]); ql[j] = qs[j] - qh[j];
        kh[j] = half_rt(ks[j]); kl[j] = ks[j] - kh[j];
        vh[j] = half_rt(vs[j]); vl[j] = vs[j] - vh[j];
    }
    uint2 t;
    t.x = f16x2(qh[0], qh[1]); t.y = f16x2(qh[2], qh[3]); *(uint2*)&gQh[i] = t;
    t.x = f16x2(ql[0], ql[1]); t.y = f16x2(ql[2], ql[3]); *(uint2*)&gQl[i] = t;
    t.x = f16x2(kh[0], kh[1]); t.y = f16x2(kh[2], kh[3]); *(uint2*)&gKh[i] = t;
    t.x = f16x2(kl[0], kl[1]); t.y = f16x2(kl[2], kl[3]); *(uint2*)&gKl[i] = t;
    t.x = f16x2(vh[0], vh[1]); t.y = f16x2(vh[2], vh[3]); *(uint2*)&gVh[i] = t;
    t.x = f16x2(vl[0], vl[1]); t.y = f16x2(vl[2], vl[3]); *(uint2*)&gVl[i] = t;
}

// Q/K/V: [B, L, H, E] -> ((b*L + l)*H + h)*E + e   (row stride H*E = 1024)
// A:     [B, H, L, S];  O: [B, L, H, E]

__global__ __launch_bounds__(256, 2)
void attn(float* __restrict__ O, float* __restrict__ A)
{
    extern __shared__ char smraw[];
    u16* Qh = (u16*)smraw;             // [64][PW]
    u16* Ql = Qh + PLANE;
    u16* KV = Ql + PLANE;              // 8 planes: stage*4 + {Kh,Kl,Vh,Vl}
    u16* Ph = KV + 8 * PLANE;          // [64][PW] rows = m, cols = s
    float* Zs = (float*)(Ph + PLANE);  // [64]

    const int mt  = (Ls / BQ - 1) - blockIdx.x;    // heavy tiles launch first
    const int h   = blockIdx.y, b = blockIdx.z;
    const int tid = threadIdx.x;
    const int l   = tid & 31, wid = tid >> 5;
    const int wm  = wid >> 2, wn = wid & 3;        // 2 x 4 warp grid, 32x16 tiles
    const int m0  = mt * BQ;
    const int bh  = b * Hh + h;

    const size_t qoff = (((size_t)b * Ls + m0) * Hh + h) * Ee;
    const size_t koff = ((size_t)b * Ls * Hh + h) * Ee;
    float* Ab = A + ((size_t)bh * Ls + m0) * (size_t)Ls;

    const int row8 = tid >> 3, seg8 = (tid & 7) * 8;   // 16B-chunk coords

    // ---- async-copy Q tile (2 planes x 64 rows x 128B) ----
    #pragma unroll
    for (int p = 0; p < 4; p++) {
        int cc  = tid + (p & 1) * 256;            // 0..511
        int row = cc >> 3, seg = (cc & 7) * 8;
        const u16* src = (p < 2 ? gQh : gQl) + qoff + (size_t)row * 1024 + seg;
        u16* dst = (p < 2 ? Qh : Ql) + row * PW + seg;
        CPA(sm32(dst), src);
    }
    // ---- prefetch K/V stage 0 (4 planes x 64 rows x 128B) ----
    #pragma unroll
    for (int p = 0; p < 8; p++) {
        int cc  = tid + (p & 1) * 256;
        int row = cc >> 3, seg = (cc & 7) * 8;
        int plane = p >> 1;
        const u16* srcb = (plane == 0 ? gKh : plane == 1 ? gKl : plane == 2 ? gVh : gVl);
        const u16* src = srcb + koff + (size_t)row * 1024 + seg;
        CPA(sm32(KV + plane * PLANE + row * PW + seg), src);
    }
    asm volatile("cp.async.commit_group;");

    if (tid < 64) Zs[tid] = 0.f;

    // ---- zero-fill fully masked A columns [m0+BQ, Ls) (overlaps async copies) ----
    if (m0 + BQ < Ls) {
        int c0  = m0 + BQ;
        int w4  = (Ls - c0) >> 2;
        int tot = BQ * w4;
        for (int idx = tid; idx < tot; idx += 256) {
            int r  = idx / w4;
            int c4 = idx - r * w4;
            *(float4*)(Ab + (size_t)r * Ls + c0 + c4 * 4) = make_float4(0.f, 0.f, 0.f, 0.f);
        }
    }

    float zp[4];
    zp[0] = zp[1] = zp[2] = zp[3] = 0.f;
    float oacc[2][2][4];
    #pragma unroll
    for (int i = 0; i < 2; i++)
        #pragma unroll
        for (int j = 0; j < 2; j++)
            #pragma unroll
            for (int k = 0; k < 4; k++) oacc[i][j][k] = 0.f;

    const u32 uQh = sm32(Qh), uQl = sm32(Ql);
    const u32 uKV = sm32(KV), uPh = sm32(Ph);
    // ldmatrix offsets (bytes)
    const u32 aOff = ((32 * wm + (l & 15)) * PW + 8 * (l >> 4)) * 2;
    const u32 bOff = ((16 * wn + 8 * ((l >> 3) & 1) + (l & 7)) * PW + 8 * (l >> 4)) * 2;
    const u32 vOff = (((l & 7) + 8 * (l >> 4)) * PW + 16 * wn + 8 * ((l >> 3) & 1)) * 2;

    for (int nt = 0; nt <= mt; nt++) {
        const int st = nt & 1;
        __syncthreads();       // prior readers of buffer st^1 are done
        if (nt < mt) {
            // ---- prefetch stage nt+1 into the other buffer ----
            const size_t base = koff + (size_t)(nt + 1) * BK * 1024;
            u16* dstb = KV + (st ^ 1) * 4 * PLANE;
            #pragma unroll
            for (int p = 0; p < 8; p++) {
                int cc  = tid + (p & 1) * 256;
                int row = cc >> 3, seg = (cc & 7) * 8;
                int plane = p >> 1;
                const u16* srcb = (plane == 0 ? gKh : plane == 1 ? gKl
                                   : plane == 2 ? gVh : gVl);
                CPA(sm32(dstb + plane * PLANE + row * PW + seg),
                    srcb + base + (size_t)row * 1024 + seg);
            }
            asm volatile("cp.async.commit_group;");
            asm volatile("cp.async.wait_group 1;");   // stage nt resident
        } else {
            asm volatile("cp.async.wait_group 0;");
        }
        __syncthreads();

        const u32 uKh = uKV + (st * 4 + 0) * PLANE * 2;
        const u32 uKl = uKV + (st * 4 + 1) * PLANE * 2;
        const u32 uVh = uKV + (st * 4 + 2) * PLANE * 2;
        const u32 uVl = uKV + (st * 4 + 3) * PLANE * 2;

        // ---- S = Q K^T via fp16x3 mma ----
        float sacc[2][2][4];
        #pragma unroll
        for (int i = 0; i < 2; i++)
            #pragma unroll
            for (int j = 0; j < 2; j++)
                #pragma unroll
                for (int k = 0; k < 4; k++) sacc[i][j][k] = 0.f;

        #pragma unroll
        for (int ks = 0; ks < 4; ks++) {
            u32 ah[2][4], al[2][4], bh4[4], bl4[4];
            ldsm4(ah[0][0], ah[0][1], ah[0][2], ah[0][3], uQh + aOff + ks * 32);
            ldsm4(ah[1][0], ah[1][1], ah[1][2], ah[1][3], uQh + aOff + 16 * PW * 2 + ks * 32);
            ldsm4(al[0][0], al[0][1], al[0][2], al[0][3], uQl + aOff + ks * 32);
            ldsm4(al[1][0], al[1][1], al[1][2], al[1][3], uQl + aOff + 16 * PW * 2 + ks * 32);
            ldsm4(bh4[0], bh4[1], bh4[2], bh4[3], uKh + bOff + ks * 32);
            ldsm4(bl4[0], bl4[1], bl4[2], bl4[3], uKl + bOff + ks * 32);
            #pragma unroll
            for (int am = 0; am < 2; am++)
                #pragma unroll
                for (int an = 0; an < 2; an++) {
                    mma16816(sacc[am][an], ah[am], bh4[an], bh4[an + 2]);   // hi*hi
                    mma16816(sacc[am][an], ah[am], bl4[an], bl4[an + 2]);   // hi*lo
                    mma16816(sacc[am][an], al[am], bh4[an], bh4[an + 2]);   // lo*hi
                }
        }

        // ---- exp2, causal mask, Z partials, A write, P (fp16) -> smem ----
        const int n0 = nt * BK;
        const bool diag = (nt == mt);
        #pragma unroll
        for (int am = 0; am < 2; am++) {
            #pragma unroll
            for (int an = 0; an < 2; an++) {
                float* d = sacc[am][an];
                int rl0 = 32 * wm + 16 * am + (l >> 2);
                int c   = 16 * wn + 8 * an + 2 * (l & 3);
                int gr0 = m0 + rl0, gc = n0 + c;
                float p0 = ex2(d[0]), p1 = ex2(d[1]);
                float p2 = ex2(d[2]), p3 = ex2(d[3]);
                if (diag) {
                    if (gc     > gr0)     p0 = 0.f;
                    if (gc + 1 > gr0)     p1 = 0.f;
                    if (gc     > gr0 + 8) p2 = 0.f;
                    if (gc + 1 > gr0 + 8) p3 = 0.f;
                }
                zp[2 * am]     += p0 + p1;
                zp[2 * am + 1] += p2 + p3;
                *(float2*)(Ab + (size_t)rl0 * Ls + gc)       = make_float2(p0, p1);
                *(float2*)(Ab + (size_t)(rl0 + 8) * Ls + gc) = make_float2(p2, p3);
                *(u32*)&Ph[rl0 * PW + c]       = f16x2(p0, p1);
                *(u32*)&Ph[(rl0 + 8) * PW + c] = f16x2(p2, p3);
            }
        }
        __syncthreads();

        // ---- O += P V via fp16 2-term mma (P * (V_hi + V_lo)) ----
        #pragma unroll
        for (int ks = 0; ks < 4; ks++) {
            u32 ah[2][4], bh4[4], bl4[4];
            ldsm4(ah[0][0], ah[0][1], ah[0][2], ah[0][3], uPh + aOff + ks * 32);
            ldsm4(ah[1][0], ah[1][1], ah[1][2], ah[1][3], uPh + aOff + 16 * PW * 2 + ks * 32);
            ldsm4t(bh4[0], bh4[1], bh4[2], bh4[3], uVh + vOff + ks * 16 * PW * 2);
            ldsm4t(bl4[0], bl4[1], bl4[2], bl4[3], uVl + vOff + ks * 16 * PW * 2);
            #pragma unroll
            for (int am = 0; am < 2; am++)
                #pragma unroll
                for (int an = 0; an < 2; an++) {
                    mma16816(oacc[am][an], ah[am], bh4[an], bh4[an + 2]);
                    mma16816(oacc[am][an], ah[am], bl4[an], bl4[an + 2]);
                }
        }
    }

    // ---- Z reduction: quad shfl + smem atomics ----
    #pragma unroll
    for (int i = 0; i < 4; i++) {
        float z = zp[i];
        z += __shfl_xor_sync(0xffffffffu, z, 1);
        z += __shfl_xor_sync(0xffffffffu, z, 2);
        if ((l & 3) == 0) {
            int rl = 32 * wm + 16 * (i >> 1) + (l >> 2) + 8 * (i & 1);
            atomicAdd(&Zs[rl], z);
        }
    }
    __syncthreads();
    if (tid < 64) Zs[tid] = 1.0f / Zs[tid];
    __syncthreads();

    // ---- O epilogue (scaled by 1/Z) ----
    #pragma unroll
    for (int am = 0; am < 2; am++) {
        int rl0 = 32 * wm + 16 * am + (l >> 2);
        float zi0 = Zs[rl0], zi1 = Zs[rl0 + 8];
        int gr0 = m0 + rl0;
        #pragma unroll
        for (int an = 0; an < 2; an++) {
            float* d = oacc[am][an];
            int e = 16 * wn + 8 * an + 2 * (l & 3);
            *(float2*)(O + (((size_t)b * Ls + gr0) * Hh + h) * Ee + e) =
                make_float2(d[0] * zi0, d[1] * zi0);
            *(float2*)(O + (((size_t)b * Ls + gr0 + 8) * Hh + h) * Ee + e) =
                make_float2(d[2] * zi1, d[3] * zi1);
        }
    }

    // ---- fused A normalization (this block's rows, lower-triangular span) ----
    {
        int w4 = (mt + 1) * 16;   // float4s per row
        for (int r = wid; r < 64; r += 8) {
            float zi = Zs[r];
            float4* row = (float4*)(Ab + (size_t)r * Ls);
            for (int c4 = l; c4 < w4; c4 += 32) {
                float4 v = row[c4];
                v.x *= zi; v.y *= zi; v.z *= zi; v.w *= zi;
                row[c4] = v;
            }
        }
    }
}

extern "C" void kernel_launch(void* const* d_in, const int* in_sizes, int n_in,
                              void* d_out, int out_size) {
    const float* Q = (const float*)d_in[0];
    const float* K = (const float*)d_in[1];
    const float* V = (const float*)d_in[2];
    float* O = (float*)d_out;
    float* A = (float*)d_out + (size_t)Bb * Ls * Hh * Ee;   // tuple order: (V, A)

    prep<<<(int)(NEL / 4 / 256), 256>>>(Q, K, V);

    int smem = 11 * PLANE * 2 + 64 * 4;   // 11 x 16-bit planes + Zs = ~99.3 KB
    cudaFuncSetAttribute(attn, cudaFuncAttributeMaxDynamicSharedMemorySize, smem);
    dim3 grid(Ls / BQ, Hh, Bb);   // 32 x 16 x 2 = 1024 blocks, heavy-first
    attn<<<grid, 256, smem>>>(O, A);
}